// round 7
// baseline (speedup 1.0000x reference)
#include <cuda_runtime.h>
#include <cuda_bf16.h>
#include <math.h>
#include <stdint.h>

// Problem constants
#define S_LEN 2048
#define BATCH 2
#define EMB   2048
#define HEADS 32
#define HDIM  64
#define MROWS (S_LEN * BATCH)          // 4096
#define QKV_N (3 * EMB)                // 6144
#define K3    6144                     // expanded K: [hi | lo | hi]
#define NIT   96                       // K3 / 64
#define MASK_NEG (-66504.0f)

// ---------------------------------------------------------------------------
// Scratch (static device globals)
// ---------------------------------------------------------------------------
__device__ float g_qkv[(size_t)MROWS * QKV_N];                 // [4096, 6144]
__device__ float g_q  [(size_t)BATCH * HEADS * S_LEN * HDIM];
__device__ float g_k  [(size_t)BATCH * HEADS * S_LEN * HDIM];
__device__ float g_v  [(size_t)BATCH * HEADS * S_LEN * HDIM];
__device__ float g_ctx[(size_t)MROWS * EMB];                   // [4096, 2048]

__device__ __nv_bfloat16 g_A3 [(size_t)MROWS * K3];            // activations (hi|lo|hi)
__device__ __nv_bfloat16 g_B3q[(size_t)QKV_N * K3];            // qkv_w^T   (hi|hi|lo)
__device__ __nv_bfloat16 g_B3o[(size_t)EMB   * K3];            // out_w^T   (hi|hi|lo)

// ---------------------------------------------------------------------------
// Helpers (sm_80-era PTX — legal at compute_103)
// ---------------------------------------------------------------------------
__device__ __forceinline__ uint32_t smem_u32(const void* p) {
    uint32_t a;
    asm("{ .reg .u64 t; cvta.to.shared.u64 t, %1; cvt.u32.u64 %0, t; }" : "=r"(a) : "l"(p));
    return a;
}
__device__ __forceinline__ void cp16(uint32_t saddr, const void* g) {
    asm volatile("cp.async.cg.shared.global [%0], [%1], 16;" :: "r"(saddr), "l"(g) : "memory");
}
__device__ __forceinline__ void cp_commit() {
    asm volatile("cp.async.commit_group;" ::: "memory");
}
__device__ __forceinline__ uint32_t sw128(uint32_t off) {
    return off ^ ((off >> 3) & 0x70);
}

#define LDSM4(r, addr) \
    asm volatile("ldmatrix.sync.aligned.m8n8.x4.shared.b16 {%0,%1,%2,%3}, [%4];" \
                 : "=r"((r)[0]), "=r"((r)[1]), "=r"((r)[2]), "=r"((r)[3]) : "r"(addr))

__device__ __forceinline__ void mma_bf16(float* d, const uint32_t* a, uint32_t b0, uint32_t b1) {
    asm volatile(
        "mma.sync.aligned.m16n8k16.row.col.f32.bf16.bf16.f32 "
        "{%0,%1,%2,%3}, {%4,%5,%6,%7}, {%8,%9}, {%0,%1,%2,%3};"
        : "+f"(d[0]), "+f"(d[1]), "+f"(d[2]), "+f"(d[3])
        : "r"(a[0]), "r"(a[1]), "r"(a[2]), "r"(a[3]), "r"(b0), "r"(b1));
}

// ---------------------------------------------------------------------------
// HMMA split-bf16 GEMM v2:  C[M=4096, N] = A3[M, K3] @ B3[N, K3]^T + bias
// CTA tile 128x256, BK=64, warp tile 64x64 (8 warps, 2x4), 3-stage cp.async.
// smem: 3 stages x (A 16KB + B 32KB) = 144KB, 1 CTA/SM.
// GROUP_M=8 supertile rasterization (1D grid).
// ---------------------------------------------------------------------------
#define STAGE_BYTES 49152u
#define GEMM_SMEM (3 * 49152)

__global__ __launch_bounds__(256, 1)
void gemm_mma_bf16(int N,
                   const __nv_bfloat16* __restrict__ A3,
                   const __nv_bfloat16* __restrict__ B3,
                   const float* __restrict__ bias,
                   float* __restrict__ C) {
    extern __shared__ char sm[];
    const int tid = threadIdx.x;
    const int wid = tid >> 5;
    const int lid = tid & 31;

    // GROUP_M=8 rasterization over (Mtiles=32) x (ntiles=N/256)
    const int ntiles = N >> 8;
    const int bid = blockIdx.x;
    const int group = bid / (8 * ntiles);
    const int rem = bid % (8 * ntiles);
    const int M0 = (group * 8 + (rem & 7)) * 128;
    const int N0 = (rem >> 3) * 256;

    const uint32_t sbase = smem_u32(sm);

    // A loader: 2 threads per 128B row (128 rows); B loader: 1 thread per row (256 rows)
    const int a_lrow  = tid >> 1;
    const int a_lhalf = (tid & 1) * 64;
    const uint32_t a_soff = (uint32_t)a_lrow * 128u + (uint32_t)a_lhalf;
    const char* Ag = (const char*)(A3 + (size_t)(M0 + a_lrow) * K3) + a_lhalf;
    const uint32_t b_soff = (uint32_t)tid * 128u;
    const char* Bg = (const char*)(B3 + (size_t)(N0 + tid) * K3);

    // warp tiling: wm in {0,64}, wn in {0,64,128,192}
    const int wm = (wid & 1) * 64;
    const int wn = (wid >> 1) * 64;
    const int a_r  = wm + (lid & 15);
    const int a_cb = (lid >> 4) * 16;
    const int b_r  = wn + (lid & 7) + ((lid >> 4) << 3);
    const int b_cb = ((lid >> 3) & 1) * 16;

    float acc[4][8][4];
#pragma unroll
    for (int i = 0; i < 4; ++i)
#pragma unroll
        for (int j = 0; j < 8; ++j)
#pragma unroll
            for (int q = 0; q < 4; ++q) acc[i][j][q] = 0.0f;

    // prologue: stages 0,1
#pragma unroll
    for (int s = 0; s < 2; ++s) {
        uint32_t ab = sbase + s * STAGE_BYTES;
        uint32_t bb = ab + 16384u;
        const char* ag = Ag + s * 128;
        const char* bg = Bg + s * 128;
#pragma unroll
        for (int i = 0; i < 4; ++i)
            cp16(ab + sw128(a_soff + i * 16), ag + i * 16);
#pragma unroll
        for (int i = 0; i < 8; ++i)
            cp16(bb + sw128(b_soff + i * 16), bg + i * 16);
        cp_commit();
    }

#pragma unroll 1
    for (int it = 0; it < NIT; ++it) {
        if (it + 1 < NIT) asm volatile("cp.async.wait_group 1;" ::: "memory");
        else              asm volatile("cp.async.wait_group 0;" ::: "memory");
        __syncthreads();

        if (it + 2 < NIT) {
            int s1 = (it + 2) % 3;
            uint32_t ab = sbase + s1 * STAGE_BYTES;
            uint32_t bb = ab + 16384u;
            const char* ag = Ag + (size_t)(it + 2) * 128;
            const char* bg = Bg + (size_t)(it + 2) * 128;
#pragma unroll
            for (int i = 0; i < 4; ++i)
                cp16(ab + sw128(a_soff + i * 16), ag + i * 16);
#pragma unroll
            for (int i = 0; i < 8; ++i)
                cp16(bb + sw128(b_soff + i * 16), bg + i * 16);
            cp_commit();
        }

        const int s = it % 3;
        const uint32_t ab = sbase + s * STAGE_BYTES;
        const uint32_t bb = ab + 16384u;

#pragma unroll
        for (int kk = 0; kk < 4; ++kk) {
            uint32_t Ar[4][4];
            uint32_t Br[4][4];
#pragma unroll
            for (int i = 0; i < 4; ++i)
                LDSM4(Ar[i], ab + sw128((uint32_t)(a_r + i * 16) * 128u + kk * 32 + a_cb));
#pragma unroll
            for (int j2 = 0; j2 < 4; ++j2)
                LDSM4(Br[j2], bb + sw128((uint32_t)(b_r + j2 * 16) * 128u + kk * 32 + b_cb));
#pragma unroll
            for (int i = 0; i < 4; ++i)
#pragma unroll
                for (int j = 0; j < 8; ++j)
                    mma_bf16(acc[i][j], Ar[i], Br[j >> 1][(j & 1) * 2], Br[j >> 1][(j & 1) * 2 + 1]);
        }
    }

    // epilogue: m16n8 fragment -> rows (lid>>2, +8), cols (lid&3)*2
    const int fr = lid >> 2;
    const int fc = (lid & 3) * 2;
#pragma unroll
    for (int j = 0; j < 8; ++j) {
        const int col = N0 + wn + j * 8 + fc;
        const float bx = bias[col];
        const float by = bias[col + 1];
#pragma unroll
        for (int i = 0; i < 4; ++i) {
            const int row = M0 + wm + i * 16 + fr;
            float2 v0 = make_float2(acc[i][j][0] + bx, acc[i][j][1] + by);
            float2 v1 = make_float2(acc[i][j][2] + bx, acc[i][j][3] + by);
            *reinterpret_cast<float2*>(C + (size_t)row * N + col) = v0;
            *reinterpret_cast<float2*>(C + (size_t)(row + 8) * N + col) = v1;
        }
    }
}

// ---------------------------------------------------------------------------
// Conversions
// ---------------------------------------------------------------------------
__global__ __launch_bounds__(256)
void convA_kernel(const float* __restrict__ src, __nv_bfloat16* __restrict__ dst) {
    int i = blockIdx.x * 256 + threadIdx.x;
    int m = i >> 9;
    int j = (i & 511) * 4;
    float4 a = *reinterpret_cast<const float4*>(src + (size_t)m * EMB + j);
    float v[4] = {a.x, a.y, a.z, a.w};
    __nv_bfloat16 h[4], l[4];
#pragma unroll
    for (int q = 0; q < 4; ++q) {
        h[q] = __float2bfloat16(v[q]);
        l[q] = __float2bfloat16(v[q] - __bfloat162float(h[q]));
    }
    __nv_bfloat16* d0 = dst + (size_t)m * K3 + j;
    __nv_bfloat162 h01 = __halves2bfloat162(h[0], h[1]);
    __nv_bfloat162 h23 = __halves2bfloat162(h[2], h[3]);
    __nv_bfloat162 l01 = __halves2bfloat162(l[0], l[1]);
    __nv_bfloat162 l23 = __halves2bfloat162(l[2], l[3]);
    *reinterpret_cast<__nv_bfloat162*>(d0 + 0) = h01;
    *reinterpret_cast<__nv_bfloat162*>(d0 + 2) = h23;
    *reinterpret_cast<__nv_bfloat162*>(d0 + 2048 + 0) = l01;
    *reinterpret_cast<__nv_bfloat162*>(d0 + 2048 + 2) = l23;
    *reinterpret_cast<__nv_bfloat162*>(d0 + 4096 + 0) = h01;
    *reinterpret_cast<__nv_bfloat162*>(d0 + 4096 + 2) = h23;
}

__global__ __launch_bounds__(1024)
void convB_kernel(const float* __restrict__ src, __nv_bfloat16* __restrict__ dst, int Ncols) {
    __shared__ float tile[32][33];
    const int k0 = blockIdx.y * 32;
    const int n0 = blockIdx.x * 32;
    const int tx = threadIdx.x;
    const int ty = threadIdx.y;
    tile[ty][tx] = src[(size_t)(k0 + ty) * Ncols + n0 + tx];
    __syncthreads();
    float v = tile[tx][ty];
    __nv_bfloat16 h = __float2bfloat16(v);
    __nv_bfloat16 lo = __float2bfloat16(v - __bfloat162float(h));
    size_t drow = (size_t)(n0 + ty) * K3 + k0 + tx;
    dst[drow + 0]    = h;
    dst[drow + 2048] = h;
    dst[drow + 4096] = lo;
}

// ---------------------------------------------------------------------------
// RoPE + split
// ---------------------------------------------------------------------------
__global__ __launch_bounds__(256)
void rope_split_kernel() {
    int idx = blockIdx.x * blockDim.x + threadIdx.x;
    int d = idx & 63;
    int h = (idx >> 6) & 31;
    int b = (idx >> 11) & 1;
    int s = idx >> 12;

    const float* base = g_qkv + (size_t)(s * BATCH + b) * QKV_N;
    int col = h * HDIM + d;

    float qv = base[col];
    float kv = base[EMB + col];
    float vv = base[2 * EMB + col];

    int i = d & 31;
    float inv_freq = __expf(-0.28782252f * (float)i);
    float ang = (float)s * inv_freq;
    float sn, cs;
    sincosf(ang, &sn, &cs);

    float qpair, kpair;
    if (d < 32) {
        qpair = -base[col + 32];
        kpair = -base[EMB + col + 32];
    } else {
        qpair = base[col - 32];
        kpair = base[EMB + col - 32];
    }

    size_t o = ((size_t)(b * HEADS + h) * S_LEN + s) * HDIM + d;
    g_q[o] = qv * cs + qpair * sn;
    g_k[o] = kv * cs + kpair * sn;
    g_v[o] = vv;
}

// ---------------------------------------------------------------------------
// Causal flash attention v3 (unchanged from round 5)
// ---------------------------------------------------------------------------
#define ATTN_SMEM (80 * 1024)

__global__ __launch_bounds__(256, 2)
void attn_kernel() {
    extern __shared__ float smf[];
    float (*Qs)[128] = reinterpret_cast<float(*)[128]>(smf);
    float (*KVs)[64] = reinterpret_cast<float(*)[64]>(smf + 8192);
    float (*Ps)[128] = reinterpret_cast<float(*)[128]>(smf + 8192 + 4096);

    const int bh = blockIdx.y;
    const int qt = (int)(gridDim.x - 1) - (int)blockIdx.x;
    const int q0 = qt * 128;
    const int t  = threadIdx.x;
    const int ty = t >> 4;
    const int tx = t & 15;
    const int r0 = ty * 8;
    const int x0 = tx * 4;

    const float* Qh = g_q + (size_t)bh * S_LEN * HDIM;
    const float* Kh = g_k + (size_t)bh * S_LEN * HDIM;
    const float* Vh = g_v + (size_t)bh * S_LEN * HDIM;

    {
        const int rr = t & 127;
        const int dg0 = t >> 7;
#pragma unroll
        for (int it = 0; it < 8; ++it) {
            int dg = dg0 + it * 2;
            float4 q4 = *reinterpret_cast<const float4*>(Qh + (size_t)(q0 + rr) * HDIM + dg * 4);
            Qs[dg * 4 + 0][rr] = q4.x;
            Qs[dg * 4 + 1][rr] = q4.y;
            Qs[dg * 4 + 2][rr] = q4.z;
            Qs[dg * 4 + 3][rr] = q4.w;
        }
    }

    const float scale = 0.125f;
    float m[8], l[8], acc[8][4];
#pragma unroll
    for (int i = 0; i < 8; ++i) {
        m[i] = -1e30f;
        l[i] = 0.0f;
#pragma unroll
        for (int j = 0; j < 4; ++j) acc[i][j] = 0.0f;
    }

    const int nkt = 2 * qt + 2;
    for (int kt = 0; kt < nkt; ++kt) {
        const int k0 = kt * 64;
        __syncthreads();

        {
            const int cc = t & 63;
            const int dg0 = t >> 6;
#pragma unroll
            for (int it = 0; it < 4; ++it) {
                int dg = dg0 + it * 4;
                float4 k4 = *reinterpret_cast<const float4*>(Kh + (size_t)(k0 + cc) * HDIM + dg * 4);
                KVs[dg * 4 + 0][cc] = k4.x;
                KVs[dg * 4 + 1][cc] = k4.y;
                KVs[dg * 4 + 2][cc] = k4.z;
                KVs[dg * 4 + 3][cc] = k4.w;
            }
        }
        __syncthreads();

        float s[8][4];
#pragma unroll
        for (int i = 0; i < 8; ++i)
#pragma unroll
            for (int j = 0; j < 4; ++j) s[i][j] = 0.0f;

#pragma unroll 4
        for (int d = 0; d < 64; ++d) {
            float4 qa = *reinterpret_cast<const float4*>(&Qs[d][r0]);
            float4 qb = *reinterpret_cast<const float4*>(&Qs[d][r0 + 4]);
            float4 kv = *reinterpret_cast<const float4*>(&KVs[d][x0]);
            s[0][0] += qa.x * kv.x; s[0][1] += qa.x * kv.y; s[0][2] += qa.x * kv.z; s[0][3] += qa.x * kv.w;
            s[1][0] += qa.y * kv.x; s[1][1] += qa.y * kv.y; s[1][2] += qa.y * kv.z; s[1][3] += qa.y * kv.w;
            s[2][0] += qa.z * kv.x; s[2][1] += qa.z * kv.y; s[2][2] += qa.z * kv.z; s[2][3] += qa.z * kv.w;
            s[3][0] += qa.w * kv.x; s[3][1] += qa.w * kv.y; s[3][2] += qa.w * kv.z; s[3][3] += qa.w * kv.w;
            s[4][0] += qb.x * kv.x; s[4][1] += qb.x * kv.y; s[4][2] += qb.x * kv.z; s[4][3] += qb.x * kv.w;
            s[5][0] += qb.y * kv.x; s[5][1] += qb.y * kv.y; s[5][2] += qb.y * kv.z; s[5][3] += qb.y * kv.w;
            s[6][0] += qb.z * kv.x; s[6][1] += qb.z * kv.y; s[6][2] += qb.z * kv.z; s[6][3] += qb.z * kv.w;
            s[7][0] += qb.w * kv.x; s[7][1] += qb.w * kv.y; s[7][2] += qb.w * kv.z; s[7][3] += qb.w * kv.w;
        }

#pragma unroll
        for (int i = 0; i < 8; ++i)
#pragma unroll
            for (int j = 0; j < 4; ++j) s[i][j] *= scale;

        if (kt >= nkt - 2) {
#pragma unroll
            for (int i = 0; i < 8; ++i)
#pragma unroll
                for (int j = 0; j < 4; ++j)
                    if (k0 + x0 + j > q0 + r0 + i) s[i][j] += MASK_NEG;
        }

#pragma unroll
        for (int i = 0; i < 8; ++i) {
            float mt = fmaxf(fmaxf(s[i][0], s[i][1]), fmaxf(s[i][2], s[i][3]));
            mt = fmaxf(mt, __shfl_xor_sync(0xffffffffu, mt, 1));
            mt = fmaxf(mt, __shfl_xor_sync(0xffffffffu, mt, 2));
            mt = fmaxf(mt, __shfl_xor_sync(0xffffffffu, mt, 4));
            mt = fmaxf(mt, __shfl_xor_sync(0xffffffffu, mt, 8));

            float mnew = fmaxf(m[i], mt);
            float corr = __expf(m[i] - mnew);
            float ps = 0.0f;
#pragma unroll
            for (int j = 0; j < 4; ++j) {
                float p = __expf(s[i][j] - mnew);
                s[i][j] = p;
                ps += p;
            }
            ps += __shfl_xor_sync(0xffffffffu, ps, 1);
            ps += __shfl_xor_sync(0xffffffffu, ps, 2);
            ps += __shfl_xor_sync(0xffffffffu, ps, 4);
            ps += __shfl_xor_sync(0xffffffffu, ps, 8);
            l[i] = l[i] * corr + ps;
            m[i] = mnew;
#pragma unroll
            for (int j = 0; j < 4; ++j) acc[i][j] *= corr;
        }

#pragma unroll
        for (int j = 0; j < 4; ++j) {
            int c = x0 + j;
            int ph = ty ^ ((c >> 2) & 15);
            float4 p0 = make_float4(s[0][j], s[1][j], s[2][j], s[3][j]);
            float4 p1 = make_float4(s[4][j], s[5][j], s[6][j], s[7][j]);
            *reinterpret_cast<float4*>(&Ps[c][ph * 8])     = p0;
            *reinterpret_cast<float4*>(&Ps[c][ph * 8 + 4]) = p1;
        }
        __syncthreads();

        {
            const int row0 = t >> 4;
            const int dq = (t & 15) * 4;
#pragma unroll
            for (int it = 0; it < 4; ++it) {
                int row = row0 + it * 16;
                *reinterpret_cast<float4*>(&KVs[row][dq]) =
                    *reinterpret_cast<const float4*>(Vh + (size_t)(k0 + row) * HDIM + dq);
            }
        }
        __syncthreads();

#pragma unroll 4
        for (int c = 0; c < 64; ++c) {
            int ph = ty ^ ((c >> 2) & 15);
            float4 pa = *reinterpret_cast<const float4*>(&Ps[c][ph * 8]);
            float4 pb = *reinterpret_cast<const float4*>(&Ps[c][ph * 8 + 4]);
            float4 vv = *reinterpret_cast<const float4*>(&KVs[c][x0]);
            acc[0][0] += pa.x * vv.x; acc[0][1] += pa.x * vv.y; acc[0][2] += pa.x * vv.z; acc[0][3] += pa.x * vv.w;
            acc[1][0] += pa.y * vv.x; acc[1][1] += pa.y * vv.y; acc[1][2] += pa.y * vv.z; acc[1][3] += pa.y * vv.w;
            acc[2][0] += pa.z * vv.x; acc[2][1] += pa.z * vv.y; acc[2][2] += pa.z * vv.z; acc[2][3] += pa.z * vv.w;
            acc[3][0] += pa.w * vv.x; acc[3][1] += pa.w * vv.y; acc[3][2] += pa.w * vv.z; acc[3][3] += pa.w * vv.w;
            acc[4][0] += pb.x * vv.x; acc[4][1] += pb.x * vv.y; acc[4][2] += pb.x * vv.z; acc[4][3] += pb.x * vv.w;
            acc[5][0] += pb.y * vv.x; acc[5][1] += pb.y * vv.y; acc[5][2] += pb.y * vv.z; acc[5][3] += pb.y * vv.w;
            acc[6][0] += pb.z * vv.x; acc[6][1] += pb.z * vv.y; acc[6][2] += pb.z * vv.z; acc[6][3] += pb.z * vv.w;
            acc[7][0] += pb.w * vv.x; acc[7][1] += pb.w * vv.y; acc[7][2] += pb.w * vv.z; acc[7][3] += pb.w * vv.w;
        }
    }

    const int b = bh >> 5;
    const int h = bh & 31;
#pragma unroll
    for (int i = 0; i < 8; ++i) {
        float inv_l = 1.0f / l[i];
        int row = q0 + r0 + i;
        float4 o;
        o.x = acc[i][0] * inv_l;
        o.y = acc[i][1] * inv_l;
        o.z = acc[i][2] * inv_l;
        o.w = acc[i][3] * inv_l;
        *reinterpret_cast<float4*>(g_ctx + (size_t)(row * BATCH + b) * EMB + h * HDIM + x0) = o;
    }
}

// ---------------------------------------------------------------------------
// Launch
// ---------------------------------------------------------------------------
extern "C" void kernel_launch(void* const* d_in, const int* in_sizes, int n_in,
                              void* d_out, int out_size) {
    const float* hs    = (const float*)d_in[0];
    const float* qkv_w = (const float*)d_in[1];
    const float* qkv_b = (const float*)d_in[2];
    const float* out_w = (const float*)d_in[3];
    const float* out_b = (const float*)d_in[4];
    float* out = (float*)d_out;

    cudaFuncSetAttribute(gemm_mma_bf16, cudaFuncAttributeMaxDynamicSharedMemorySize, GEMM_SMEM);
    cudaFuncSetAttribute(attn_kernel, cudaFuncAttributeMaxDynamicSharedMemorySize, ATTN_SMEM);

    float *qkv, *ctx;
    __nv_bfloat16 *A3, *B3q, *B3o;
    cudaGetSymbolAddress((void**)&qkv, g_qkv);
    cudaGetSymbolAddress((void**)&ctx, g_ctx);
    cudaGetSymbolAddress((void**)&A3,  g_A3);
    cudaGetSymbolAddress((void**)&B3q, g_B3q);
    cudaGetSymbolAddress((void**)&B3o, g_B3o);

    // Weight conversions (transpose + hi/lo split)
    {
        dim3 blk(32, 32);
        convB_kernel<<<dim3(QKV_N / 32, EMB / 32), blk>>>(qkv_w, B3q, QKV_N);
        convB_kernel<<<dim3(EMB / 32, EMB / 32), blk>>>(out_w, B3o, EMB);
    }
    convA_kernel<<<MROWS * 512 / 256, 256>>>(hs, A3);

    // 1. QKV projection (HMMA, 128x256 tiles): 32 M-tiles x 24 N-tiles
    gemm_mma_bf16<<<(MROWS / 128) * (QKV_N / 256), 256, GEMM_SMEM>>>(QKV_N, A3, B3q, qkv_b, qkv);

    // 2. RoPE + split
    rope_split_kernel<<<(S_LEN * BATCH * HEADS * HDIM) / 256, 256>>>();

    // 3. Causal attention
    attn_kernel<<<dim3(S_LEN / 128, BATCH * HEADS), 256, ATTN_SMEM>>>();

    // 4. ctx conversion + output projection (HMMA): 32 x 8 tiles
    convA_kernel<<<MROWS * 512 / 256, 256>>>(ctx, A3);
    gemm_mma_bf16<<<(MROWS / 128) * (EMB / 256), 256, GEMM_SMEM>>>(EMB, A3, B3o, out_b, out);
}

// round 8
// speedup vs baseline: 1.1013x; 1.1013x over previous
#include <cuda_runtime.h>
#include <cuda_bf16.h>
#include <math.h>
#include <stdint.h>

// Problem constants
#define S_LEN 2048
#define BATCH 2
#define EMB   2048
#define HEADS 32
#define HDIM  64
#define MROWS (S_LEN * BATCH)          // 4096
#define QKV_N (3 * EMB)                // 6144
#define K2    4096                     // packed K: chunk-interleaved [hi32|lo32]
#define NIT2  64                       // 2048 / 32 chunks
#define MASK_NEG (-66504.0f)

// ---------------------------------------------------------------------------
// Scratch (static device globals)
// ---------------------------------------------------------------------------
__device__ float g_qkv[(size_t)MROWS * QKV_N];                 // [4096, 6144]
__device__ float g_q  [(size_t)BATCH * HEADS * S_LEN * HDIM];
__device__ float g_k  [(size_t)BATCH * HEADS * S_LEN * HDIM];
__device__ float g_v  [(size_t)BATCH * HEADS * S_LEN * HDIM];
__device__ float g_ctx[(size_t)MROWS * EMB];                   // [4096, 2048]

__device__ __nv_bfloat16 g_A2 [(size_t)MROWS * K2];            // 32MB activations
__device__ __nv_bfloat16 g_B2q[(size_t)QKV_N * K2];            // 48MB qkv_w^T
__device__ __nv_bfloat16 g_B2o[(size_t)EMB   * K2];            // 16MB out_w^T

// ---------------------------------------------------------------------------
// Helpers (sm_80-era PTX — legal at compute_103)
// ---------------------------------------------------------------------------
__device__ __forceinline__ uint32_t smem_u32(const void* p) {
    uint32_t a;
    asm("{ .reg .u64 t; cvta.to.shared.u64 t, %1; cvt.u32.u64 %0, t; }" : "=r"(a) : "l"(p));
    return a;
}
__device__ __forceinline__ void cp16(uint32_t saddr, const void* g) {
    asm volatile("cp.async.cg.shared.global [%0], [%1], 16;" :: "r"(saddr), "l"(g) : "memory");
}
__device__ __forceinline__ void cp_commit() {
    asm volatile("cp.async.commit_group;" ::: "memory");
}
__device__ __forceinline__ uint32_t sw128(uint32_t off) {
    return off ^ ((off >> 3) & 0x70);
}

#define LDSM4(r, addr) \
    asm volatile("ldmatrix.sync.aligned.m8n8.x4.shared.b16 {%0,%1,%2,%3}, [%4];" \
                 : "=r"((r)[0]), "=r"((r)[1]), "=r"((r)[2]), "=r"((r)[3]) : "r"(addr))

__device__ __forceinline__ void mma_bf16(float* d, const uint32_t* a, uint32_t b0, uint32_t b1) {
    asm volatile(
        "mma.sync.aligned.m16n8k16.row.col.f32.bf16.bf16.f32 "
        "{%0,%1,%2,%3}, {%4,%5,%6,%7}, {%8,%9}, {%0,%1,%2,%3};"
        : "+f"(d[0]), "+f"(d[1]), "+f"(d[2]), "+f"(d[3])
        : "r"(a[0]), "r"(a[1]), "r"(a[2]), "r"(a[3]), "r"(b0), "r"(b1));
}

// ---------------------------------------------------------------------------
// HMMA split-bf16 GEMM v3:  C = A@B^T + bias with 3-product fused chunks.
// A2/B2 rows: per 32-K chunk a 128B line [hi32 | lo32] (bf16).
// CTA tile 128x128, BK=32 (one chunk), 3-stage cp.async, stage=32KB,
// 2 CTAs/SM. Warp tile 64x32 (8 warps, 2x4). Per k16: 12 LDSM -> 48 MMA
// (acc += Ah*Bh + Ah*Bl + Al*Bh; Al*Bl term dropped, ~1e-5 rel).
// ---------------------------------------------------------------------------
#define STAGE_BYTES 32768u
#define GEMM_SMEM (3 * 32768)

__global__ __launch_bounds__(256, 2)
void gemm_mma_bf16(int N,
                   const __nv_bfloat16* __restrict__ A2,
                   const __nv_bfloat16* __restrict__ B2,
                   const float* __restrict__ bias,
                   float* __restrict__ C) {
    extern __shared__ char sm[];
    const int tid = threadIdx.x;
    const int wid = tid >> 5;
    const int lid = tid & 31;
    const int M0 = blockIdx.y * 128;
    const int N0 = blockIdx.x * 128;
    const uint32_t sbase = smem_u32(sm);

    // loader: one 128B row per thread. tid<128 -> A row, tid>=128 -> B row.
    const int lrow = tid & 127;
    const int lmat = tid >> 7;                        // 0=A, 1=B
    const uint32_t tile_off = (uint32_t)lmat * 16384u;
    const uint32_t soff = (uint32_t)lrow * 128u;
    const char* Gsrc = lmat
        ? (const char*)(B2 + (size_t)(N0 + lrow) * K2)
        : (const char*)(A2 + (size_t)(M0 + lrow) * K2);

    // warp tiling: wm in {0,64}, wn in {0,32,64,96}
    const int wm = (wid & 1) * 64;
    const int wn = (wid >> 1) * 32;
    const int a_r  = wm + (lid & 15);
    const int a_cb = (lid >> 4) * 16;                 // 0 or 16 within 32B k16 block
    const int b_r  = wn + (lid & 7) + ((lid >> 4) << 3);
    const int b_cb = ((lid >> 3) & 1) * 16;

    float acc[4][4][4];
#pragma unroll
    for (int i = 0; i < 4; ++i)
#pragma unroll
        for (int j = 0; j < 4; ++j)
#pragma unroll
            for (int q = 0; q < 4; ++q) acc[i][j][q] = 0.0f;

    // prologue: stages 0,1
#pragma unroll
    for (int s = 0; s < 2; ++s) {
        uint32_t stg = sbase + s * STAGE_BYTES + tile_off;
        const char* g = Gsrc + s * 128;
#pragma unroll
        for (int i = 0; i < 8; ++i)
            cp16(stg + sw128(soff + i * 16), g + i * 16);
        cp_commit();
    }

#pragma unroll 1
    for (int it = 0; it < NIT2; ++it) {
        if (it + 1 < NIT2) asm volatile("cp.async.wait_group 1;" ::: "memory");
        else               asm volatile("cp.async.wait_group 0;" ::: "memory");
        __syncthreads();

        if (it + 2 < NIT2) {
            int s1 = (it + 2) % 3;
            uint32_t stg = sbase + s1 * STAGE_BYTES + tile_off;
            const char* g = Gsrc + (size_t)(it + 2) * 128;
#pragma unroll
            for (int i = 0; i < 8; ++i)
                cp16(stg + sw128(soff + i * 16), g + i * 16);
            cp_commit();
        }

        const int s = it % 3;
        const uint32_t ab = sbase + s * STAGE_BYTES;          // A tile
        const uint32_t bb = ab + 16384u;                      // B tile

        // rows are 128B = [hi32 | lo32] per chunk; kk in {0,1} selects k16
#pragma unroll
        for (int kk = 0; kk < 2; ++kk) {
            uint32_t Ah[4][4], Bh[2][4], Bl[2][4];
#pragma unroll
            for (int i = 0; i < 4; ++i)
                LDSM4(Ah[i], ab + sw128((uint32_t)(a_r + i * 16) * 128u + kk * 32 + a_cb));
#pragma unroll
            for (int j2 = 0; j2 < 2; ++j2)
                LDSM4(Bh[j2], bb + sw128((uint32_t)(b_r + j2 * 16) * 128u + kk * 32 + b_cb));
#pragma unroll
            for (int j2 = 0; j2 < 2; ++j2)
                LDSM4(Bl[j2], bb + sw128((uint32_t)(b_r + j2 * 16) * 128u + 64u + kk * 32 + b_cb));

            // Ah * Bh  and  Ah * Bl
#pragma unroll
            for (int i = 0; i < 4; ++i)
#pragma unroll
                for (int j = 0; j < 4; ++j)
                    mma_bf16(acc[i][j], Ah[i], Bh[j >> 1][(j & 1) * 2], Bh[j >> 1][(j & 1) * 2 + 1]);
#pragma unroll
            for (int i = 0; i < 4; ++i)
#pragma unroll
                for (int j = 0; j < 4; ++j)
                    mma_bf16(acc[i][j], Ah[i], Bl[j >> 1][(j & 1) * 2], Bl[j >> 1][(j & 1) * 2 + 1]);

            // Al (reuses Ah's register space after it dies) * Bh
            uint32_t Al[4][4];
#pragma unroll
            for (int i = 0; i < 4; ++i)
                LDSM4(Al[i], ab + sw128((uint32_t)(a_r + i * 16) * 128u + 64u + kk * 32 + a_cb));
#pragma unroll
            for (int i = 0; i < 4; ++i)
#pragma unroll
                for (int j = 0; j < 4; ++j)
                    mma_bf16(acc[i][j], Al[i], Bh[j >> 1][(j & 1) * 2], Bh[j >> 1][(j & 1) * 2 + 1]);
        }
    }

    // epilogue: m16n8 fragment -> rows (lid>>2, +8), cols (lid&3)*2
    const int fr = lid >> 2;
    const int fc = (lid & 3) * 2;
#pragma unroll
    for (int j = 0; j < 4; ++j) {
        const int col = N0 + wn + j * 8 + fc;
        const float bx = bias[col];
        const float by = bias[col + 1];
#pragma unroll
        for (int i = 0; i < 4; ++i) {
            const int row = M0 + wm + i * 16 + fr;
            float2 v0 = make_float2(acc[i][j][0] + bx, acc[i][j][1] + by);
            float2 v1 = make_float2(acc[i][j][2] + bx, acc[i][j][3] + by);
            *reinterpret_cast<float2*>(C + (size_t)row * N + col) = v0;
            *reinterpret_cast<float2*>(C + (size_t)(row + 8) * N + col) = v1;
        }
    }
}

// ---------------------------------------------------------------------------
// Conversions -> chunk-interleaved [hi32|lo32] layout
// ---------------------------------------------------------------------------
// A: fp32 [M,2048] -> A2 [M][64 chunks][hi32|lo32]
__global__ __launch_bounds__(256)
void convA_kernel(const float* __restrict__ src, __nv_bfloat16* __restrict__ dst) {
    int i = blockIdx.x * 256 + threadIdx.x;   // M*512 threads
    int m = i >> 9;
    int j = (i & 511) * 4;                    // k index 0..2044
    int c = j >> 5;                           // chunk
    int pos = j & 31;                         // position in chunk (mult of 4)
    float4 a = *reinterpret_cast<const float4*>(src + (size_t)m * EMB + j);
    float v[4] = {a.x, a.y, a.z, a.w};
    __nv_bfloat16 h[4], l[4];
#pragma unroll
    for (int q = 0; q < 4; ++q) {
        h[q] = __float2bfloat16(v[q]);
        l[q] = __float2bfloat16(v[q] - __bfloat162float(h[q]));
    }
    __nv_bfloat16* d0 = dst + (size_t)m * K2 + c * 64 + pos;
    *reinterpret_cast<__nv_bfloat162*>(d0 + 0)      = __halves2bfloat162(h[0], h[1]);
    *reinterpret_cast<__nv_bfloat162*>(d0 + 2)      = __halves2bfloat162(h[2], h[3]);
    *reinterpret_cast<__nv_bfloat162*>(d0 + 32 + 0) = __halves2bfloat162(l[0], l[1]);
    *reinterpret_cast<__nv_bfloat162*>(d0 + 32 + 2) = __halves2bfloat162(l[2], l[3]);
}

// B: fp32 [2048, Ncols] -> transposed B2 [Ncols][64 chunks][hi32|lo32]
__global__ __launch_bounds__(1024)
void convB_kernel(const float* __restrict__ src, __nv_bfloat16* __restrict__ dst, int Ncols) {
    __shared__ float tile[32][33];
    const int k0 = blockIdx.y * 32;
    const int n0 = blockIdx.x * 32;
    const int tx = threadIdx.x;
    const int ty = threadIdx.y;
    tile[ty][tx] = src[(size_t)(k0 + ty) * Ncols + n0 + tx];
    __syncthreads();
    float v = tile[tx][ty];                   // element (k=k0+tx, n=n0+ty)
    __nv_bfloat16 h = __float2bfloat16(v);
    __nv_bfloat16 lo = __float2bfloat16(v - __bfloat162float(h));
    size_t base = (size_t)(n0 + ty) * K2 + (size_t)(k0 >> 5) * 64 + tx;
    dst[base]      = h;
    dst[base + 32] = lo;
}

// ---------------------------------------------------------------------------
// RoPE + split
// ---------------------------------------------------------------------------
__global__ __launch_bounds__(256)
void rope_split_kernel() {
    int idx = blockIdx.x * blockDim.x + threadIdx.x;
    int d = idx & 63;
    int h = (idx >> 6) & 31;
    int b = (idx >> 11) & 1;
    int s = idx >> 12;

    const float* base = g_qkv + (size_t)(s * BATCH + b) * QKV_N;
    int col = h * HDIM + d;

    float qv = base[col];
    float kv = base[EMB + col];
    float vv = base[2 * EMB + col];

    int i = d & 31;
    float inv_freq = __expf(-0.28782252f * (float)i);
    float ang = (float)s * inv_freq;
    float sn, cs;
    sincosf(ang, &sn, &cs);

    float qpair, kpair;
    if (d < 32) {
        qpair = -base[col + 32];
        kpair = -base[EMB + col + 32];
    } else {
        qpair = base[col - 32];
        kpair = base[EMB + col - 32];
    }

    size_t o = ((size_t)(b * HEADS + h) * S_LEN + s) * HDIM + d;
    g_q[o] = qv * cs + qpair * sn;
    g_k[o] = kv * cs + kpair * sn;
    g_v[o] = vv;
}

// ---------------------------------------------------------------------------
// Causal flash attention v3 (unchanged — best at 2634us)
// ---------------------------------------------------------------------------
#define ATTN_SMEM (80 * 1024)

__global__ __launch_bounds__(256, 2)
void attn_kernel() {
    extern __shared__ float smf[];
    float (*Qs)[128] = reinterpret_cast<float(*)[128]>(smf);
    float (*KVs)[64] = reinterpret_cast<float(*)[64]>(smf + 8192);
    float (*Ps)[128] = reinterpret_cast<float(*)[128]>(smf + 8192 + 4096);

    const int bh = blockIdx.y;
    const int qt = (int)(gridDim.x - 1) - (int)blockIdx.x;
    const int q0 = qt * 128;
    const int t  = threadIdx.x;
    const int ty = t >> 4;
    const int tx = t & 15;
    const int r0 = ty * 8;
    const int x0 = tx * 4;

    const float* Qh = g_q + (size_t)bh * S_LEN * HDIM;
    const float* Kh = g_k + (size_t)bh * S_LEN * HDIM;
    const float* Vh = g_v + (size_t)bh * S_LEN * HDIM;

    {
        const int rr = t & 127;
        const int dg0 = t >> 7;
#pragma unroll
        for (int it = 0; it < 8; ++it) {
            int dg = dg0 + it * 2;
            float4 q4 = *reinterpret_cast<const float4*>(Qh + (size_t)(q0 + rr) * HDIM + dg * 4);
            Qs[dg * 4 + 0][rr] = q4.x;
            Qs[dg * 4 + 1][rr] = q4.y;
            Qs[dg * 4 + 2][rr] = q4.z;
            Qs[dg * 4 + 3][rr] = q4.w;
        }
    }

    const float scale = 0.125f;
    float m[8], l[8], acc[8][4];
#pragma unroll
    for (int i = 0; i < 8; ++i) {
        m[i] = -1e30f;
        l[i] = 0.0f;
#pragma unroll
        for (int j = 0; j < 4; ++j) acc[i][j] = 0.0f;
    }

    const int nkt = 2 * qt + 2;
    for (int kt = 0; kt < nkt; ++kt) {
        const int k0 = kt * 64;
        __syncthreads();

        {
            const int cc = t & 63;
            const int dg0 = t >> 6;
#pragma unroll
            for (int it = 0; it < 4; ++it) {
                int dg = dg0 + it * 4;
                float4 k4 = *reinterpret_cast<const float4*>(Kh + (size_t)(k0 + cc) * HDIM + dg * 4);
                KVs[dg * 4 + 0][cc] = k4.x;
                KVs[dg * 4 + 1][cc] = k4.y;
                KVs[dg * 4 + 2][cc] = k4.z;
                KVs[dg * 4 + 3][cc] = k4.w;
            }
        }
        __syncthreads();

        float s[8][4];
#pragma unroll
        for (int i = 0; i < 8; ++i)
#pragma unroll
            for (int j = 0; j < 4; ++j) s[i][j] = 0.0f;

#pragma unroll 4
        for (int d = 0; d < 64; ++d) {
            float4 qa = *reinterpret_cast<const float4*>(&Qs[d][r0]);
            float4 qb = *reinterpret_cast<const float4*>(&Qs[d][r0 + 4]);
            float4 kv = *reinterpret_cast<const float4*>(&KVs[d][x0]);
            s[0][0] += qa.x * kv.x; s[0][1] += qa.x * kv.y; s[0][2] += qa.x * kv.z; s[0][3] += qa.x * kv.w;
            s[1][0] += qa.y * kv.x; s[1][1] += qa.y * kv.y; s[1][2] += qa.y * kv.z; s[1][3] += qa.y * kv.w;
            s[2][0] += qa.z * kv.x; s[2][1] += qa.z * kv.y; s[2][2] += qa.z * kv.z; s[2][3] += qa.z * kv.w;
            s[3][0] += qa.w * kv.x; s[3][1] += qa.w * kv.y; s[3][2] += qa.w * kv.z; s[3][3] += qa.w * kv.w;
            s[4][0] += qb.x * kv.x; s[4][1] += qb.x * kv.y; s[4][2] += qb.x * kv.z; s[4][3] += qb.x * kv.w;
            s[5][0] += qb.y * kv.x; s[5][1] += qb.y * kv.y; s[5][2] += qb.y * kv.z; s[5][3] += qb.y * kv.w;
            s[6][0] += qb.z * kv.x; s[6][1] += qb.z * kv.y; s[6][2] += qb.z * kv.z; s[6][3] += qb.z * kv.w;
            s[7][0] += qb.w * kv.x; s[7][1] += qb.w * kv.y; s[7][2] += qb.w * kv.z; s[7][3] += qb.w * kv.w;
        }

#pragma unroll
        for (int i = 0; i < 8; ++i)
#pragma unroll
            for (int j = 0; j < 4; ++j) s[i][j] *= scale;

        if (kt >= nkt - 2) {
#pragma unroll
            for (int i = 0; i < 8; ++i)
#pragma unroll
                for (int j = 0; j < 4; ++j)
                    if (k0 + x0 + j > q0 + r0 + i) s[i][j] += MASK_NEG;
        }

#pragma unroll
        for (int i = 0; i < 8; ++i) {
            float mt = fmaxf(fmaxf(s[i][0], s[i][1]), fmaxf(s[i][2], s[i][3]));
            mt = fmaxf(mt, __shfl_xor_sync(0xffffffffu, mt, 1));
            mt = fmaxf(mt, __shfl_xor_sync(0xffffffffu, mt, 2));
            mt = fmaxf(mt, __shfl_xor_sync(0xffffffffu, mt, 4));
            mt = fmaxf(mt, __shfl_xor_sync(0xffffffffu, mt, 8));

            float mnew = fmaxf(m[i], mt);
            float corr = __expf(m[i] - mnew);
            float ps = 0.0f;
#pragma unroll
            for (int j = 0; j < 4; ++j) {
                float p = __expf(s[i][j] - mnew);
                s[i][j] = p;
                ps += p;
            }
            ps += __shfl_xor_sync(0xffffffffu, ps, 1);
            ps += __shfl_xor_sync(0xffffffffu, ps, 2);
            ps += __shfl_xor_sync(0xffffffffu, ps, 4);
            ps += __shfl_xor_sync(0xffffffffu, ps, 8);
            l[i] = l[i] * corr + ps;
            m[i] = mnew;
#pragma unroll
            for (int j = 0; j < 4; ++j) acc[i][j] *= corr;
        }

#pragma unroll
        for (int j = 0; j < 4; ++j) {
            int c = x0 + j;
            int ph = ty ^ ((c >> 2) & 15);
            float4 p0 = make_float4(s[0][j], s[1][j], s[2][j], s[3][j]);
            float4 p1 = make_float4(s[4][j], s[5][j], s[6][j], s[7][j]);
            *reinterpret_cast<float4*>(&Ps[c][ph * 8])     = p0;
            *reinterpret_cast<float4*>(&Ps[c][ph * 8 + 4]) = p1;
        }
        __syncthreads();

        {
            const int row0 = t >> 4;
            const int dq = (t & 15) * 4;
#pragma unroll
            for (int it = 0; it < 4; ++it) {
                int row = row0 + it * 16;
                *reinterpret_cast<float4*>(&KVs[row][dq]) =
                    *reinterpret_cast<const float4*>(Vh + (size_t)(k0 + row) * HDIM + dq);
            }
        }
        __syncthreads();

#pragma unroll 4
        for (int c = 0; c < 64; ++c) {
            int ph = ty ^ ((c >> 2) & 15);
            float4 pa = *reinterpret_cast<const float4*>(&Ps[c][ph * 8]);
            float4 pb = *reinterpret_cast<const float4*>(&Ps[c][ph * 8 + 4]);
            float4 vv = *reinterpret_cast<const float4*>(&KVs[c][x0]);
            acc[0][0] += pa.x * vv.x; acc[0][1] += pa.x * vv.y; acc[0][2] += pa.x * vv.z; acc[0][3] += pa.x * vv.w;
            acc[1][0] += pa.y * vv.x; acc[1][1] += pa.y * vv.y; acc[1][2] += pa.y * vv.z; acc[1][3] += pa.y * vv.w;
            acc[2][0] += pa.z * vv.x; acc[2][1] += pa.z * vv.y; acc[2][2] += pa.z * vv.z; acc[2][3] += pa.z * vv.w;
            acc[3][0] += pa.w * vv.x; acc[3][1] += pa.w * vv.y; acc[3][2] += pa.w * vv.z; acc[3][3] += pa.w * vv.w;
            acc[4][0] += pb.x * vv.x; acc[4][1] += pb.x * vv.y; acc[4][2] += pb.x * vv.z; acc[4][3] += pb.x * vv.w;
            acc[5][0] += pb.y * vv.x; acc[5][1] += pb.y * vv.y; acc[5][2] += pb.y * vv.z; acc[5][3] += pb.y * vv.w;
            acc[6][0] += pb.z * vv.x; acc[6][1] += pb.z * vv.y; acc[6][2] += pb.z * vv.z; acc[6][3] += pb.z * vv.w;
            acc[7][0] += pb.w * vv.x; acc[7][1] += pb.w * vv.y; acc[7][2] += pb.w * vv.z; acc[7][3] += pb.w * vv.w;
        }
    }

    const int b = bh >> 5;
    const int h = bh & 31;
#pragma unroll
    for (int i = 0; i < 8; ++i) {
        float inv_l = 1.0f / l[i];
        int row = q0 + r0 + i;
        float4 o;
        o.x = acc[i][0] * inv_l;
        o.y = acc[i][1] * inv_l;
        o.z = acc[i][2] * inv_l;
        o.w = acc[i][3] * inv_l;
        *reinterpret_cast<float4*>(g_ctx + (size_t)(row * BATCH + b) * EMB + h * HDIM + x0) = o;
    }
}

// ---------------------------------------------------------------------------
// Launch
// ---------------------------------------------------------------------------
extern "C" void kernel_launch(void* const* d_in, const int* in_sizes, int n_in,
                              void* d_out, int out_size) {
    const float* hs    = (const float*)d_in[0];
    const float* qkv_w = (const float*)d_in[1];
    const float* qkv_b = (const float*)d_in[2];
    const float* out_w = (const float*)d_in[3];
    const float* out_b = (const float*)d_in[4];
    float* out = (float*)d_out;

    cudaFuncSetAttribute(gemm_mma_bf16, cudaFuncAttributeMaxDynamicSharedMemorySize, GEMM_SMEM);
    cudaFuncSetAttribute(attn_kernel, cudaFuncAttributeMaxDynamicSharedMemorySize, ATTN_SMEM);

    float *qkv, *ctx;
    __nv_bfloat16 *A2, *B2q, *B2o;
    cudaGetSymbolAddress((void**)&qkv, g_qkv);
    cudaGetSymbolAddress((void**)&ctx, g_ctx);
    cudaGetSymbolAddress((void**)&A2,  g_A2);
    cudaGetSymbolAddress((void**)&B2q, g_B2q);
    cudaGetSymbolAddress((void**)&B2o, g_B2o);

    // Weight conversions (transpose + hi/lo chunk-interleave)
    {
        dim3 blk(32, 32);
        convB_kernel<<<dim3(QKV_N / 32, EMB / 32), blk>>>(qkv_w, B2q, QKV_N);
        convB_kernel<<<dim3(EMB / 32, EMB / 32), blk>>>(out_w, B2o, EMB);
    }
    convA_kernel<<<MROWS * 512 / 256, 256>>>(hs, A2);

    // 1. QKV projection (HMMA fused 3-product)
    gemm_mma_bf16<<<dim3(QKV_N / 128, MROWS / 128), 256, GEMM_SMEM>>>(QKV_N, A2, B2q, qkv_b, qkv);

    // 2. RoPE + split
    rope_split_kernel<<<(S_LEN * BATCH * HEADS * HDIM) / 256, 256>>>();

    // 3. Causal attention
    attn_kernel<<<dim3(S_LEN / 128, BATCH * HEADS), 256, ATTN_SMEM>>>();

    // 4. ctx conversion + output projection
    convA_kernel<<<MROWS * 512 / 256, 256>>>(ctx, A2);
    gemm_mma_bf16<<<dim3(EMB / 128, MROWS / 128), 256, GEMM_SMEM>>>(EMB, A2, B2o, out_b, out);
}

// round 10
// speedup vs baseline: 1.6643x; 1.5112x over previous
#include <cuda_runtime.h>
#include <cuda_bf16.h>
#include <math.h>
#include <stdint.h>

// Problem constants
#define S_LEN 2048
#define BATCH 2
#define EMB   2048
#define HEADS 32
#define HDIM  64
#define MROWS (S_LEN * BATCH)          // 4096
#define QKV_N (3 * EMB)                // 6144
#define K3    6144                     // expanded K: [hi | lo | hi]
#define NIT   96                       // K3 / 64
#define MASK_NEG (-66504.0f)

// ---------------------------------------------------------------------------
// Scratch (static device globals)
// ---------------------------------------------------------------------------
__device__ float g_qkv[(size_t)MROWS * QKV_N];                 // [4096, 6144]
__device__ float g_ctx[(size_t)MROWS * EMB];                   // [4096, 2048]

__device__ __nv_bfloat16 g_A3 [(size_t)MROWS * K3];            // activations (hi|lo|hi)
__device__ __nv_bfloat16 g_B3q[(size_t)QKV_N * K3];            // qkv_w^T   (hi|hi|lo)
__device__ __nv_bfloat16 g_B3o[(size_t)EMB   * K3];            // out_w^T   (hi|hi|lo)

#define QKVLEN ((size_t)BATCH * HEADS * S_LEN * HDIM)
__device__ __nv_bfloat16 g_qb [QKVLEN];   // rope(Q) * 0.125, bf16
__device__ __nv_bfloat16 g_kb [QKVLEN];   // rope(K), bf16
__device__ __nv_bfloat16 g_vhb[QKVLEN];   // V hi
__device__ __nv_bfloat16 g_vlb[QKVLEN];   // V lo

// ---------------------------------------------------------------------------
// Helpers (sm_80-era PTX — legal at compute_103)
// ---------------------------------------------------------------------------
__device__ __forceinline__ uint32_t smem_u32(const void* p) {
    uint32_t a;
    asm("{ .reg .u64 t; cvta.to.shared.u64 t, %1; cvt.u32.u64 %0, t; }" : "=r"(a) : "l"(p));
    return a;
}
__device__ __forceinline__ void cp16(uint32_t saddr, const void* g) {
    asm volatile("cp.async.cg.shared.global [%0], [%1], 16;" :: "r"(saddr), "l"(g) : "memory");
}
__device__ __forceinline__ void cp_commit() {
    asm volatile("cp.async.commit_group;" ::: "memory");
}
__device__ __forceinline__ uint32_t sw128(uint32_t off) {
    return off ^ ((off >> 3) & 0x70);
}

#define LDSM4(r, addr) \
    asm volatile("ldmatrix.sync.aligned.m8n8.x4.shared.b16 {%0,%1,%2,%3}, [%4];" \
                 : "=r"((r)[0]), "=r"((r)[1]), "=r"((r)[2]), "=r"((r)[3]) : "r"(addr))

#define LDSM4T(r, addr) \
    asm volatile("ldmatrix.sync.aligned.m8n8.x4.trans.shared.b16 {%0,%1,%2,%3}, [%4];" \
                 : "=r"((r)[0]), "=r"((r)[1]), "=r"((r)[2]), "=r"((r)[3]) : "r"(addr))

__device__ __forceinline__ void mma_bf16(float* d, const uint32_t* a, uint32_t b0, uint32_t b1) {
    asm volatile(
        "mma.sync.aligned.m16n8k16.row.col.f32.bf16.bf16.f32 "
        "{%0,%1,%2,%3}, {%4,%5,%6,%7}, {%8,%9}, {%0,%1,%2,%3};"
        : "+f"(d[0]), "+f"(d[1]), "+f"(d[2]), "+f"(d[3])
        : "r"(a[0]), "r"(a[1]), "r"(a[2]), "r"(a[3]), "r"(b0), "r"(b1));
}

__device__ __forceinline__ uint32_t packlo(float a, float b, float& ra, float& rb) {
    __nv_bfloat162 h = __floats2bfloat162_rn(a, b);
    ra = a - __bfloat162float(__low2bfloat16(h));
    rb = b - __bfloat162float(__high2bfloat16(h));
    return *reinterpret_cast<uint32_t*>(&h);
}
__device__ __forceinline__ uint32_t packb(float a, float b) {
    __nv_bfloat162 h = __floats2bfloat162_rn(a, b);
    return *reinterpret_cast<uint32_t*>(&h);
}

// ---------------------------------------------------------------------------
// HMMA split-bf16 GEMM (exact round-5 version — best known):
// C[M=4096, N] = A3[M, K3] @ B3[N, K3]^T + bias
// CTA tile 128x128, BK=64, 3-stage cp.async pipeline, 2 CTAs/SM.
// ---------------------------------------------------------------------------
#define GEMM_SMEM (3 * 32768)

__global__ __launch_bounds__(256, 2)
void gemm_mma_bf16(int N,
                   const __nv_bfloat16* __restrict__ A3,
                   const __nv_bfloat16* __restrict__ B3,
                   const float* __restrict__ bias,
                   float* __restrict__ C) {
    extern __shared__ char sm[];
    const int tid = threadIdx.x;
    const int wid = tid >> 5;
    const int lid = tid & 31;
    const int M0 = blockIdx.y * 128;
    const int N0 = blockIdx.x * 128;
    const uint32_t sbase = smem_u32(sm);

    const int lrow  = tid >> 1;
    const int lhalf = (tid & 1) * 64;
    const uint32_t soff = (uint32_t)lrow * 128u + (uint32_t)lhalf;
    const char* Ag = (const char*)(A3 + (size_t)(M0 + lrow) * K3) + lhalf;
    const char* Bg = (const char*)(B3 + (size_t)(N0 + lrow) * K3) + lhalf;

    const int wm = (wid & 1) * 64;
    const int wn = (wid >> 1) * 32;
    const int a_r  = wm + (lid & 15);
    const int a_cb = (lid >> 4) * 16;
    const int b_r  = wn + (lid & 7) + ((lid >> 4) << 3);
    const int b_cb = ((lid >> 3) & 1) * 16;

    float acc[4][4][4];
#pragma unroll
    for (int i = 0; i < 4; ++i)
#pragma unroll
        for (int j = 0; j < 4; ++j)
#pragma unroll
            for (int q = 0; q < 4; ++q) acc[i][j][q] = 0.0f;

#pragma unroll
    for (int s = 0; s < 2; ++s) {
        uint32_t ab = sbase + s * 32768u;
        uint32_t bb = ab + 16384u;
        const char* ag = Ag + s * 128;
        const char* bg = Bg + s * 128;
#pragma unroll
        for (int i = 0; i < 4; ++i) {
            cp16(ab + sw128(soff + i * 16), ag + i * 16);
            cp16(bb + sw128(soff + i * 16), bg + i * 16);
        }
        cp_commit();
    }

#pragma unroll 1
    for (int it = 0; it < NIT; ++it) {
        if (it + 1 < NIT) asm volatile("cp.async.wait_group 1;" ::: "memory");
        else              asm volatile("cp.async.wait_group 0;" ::: "memory");
        __syncthreads();

        if (it + 2 < NIT) {
            int s1 = (it + 2) % 3;
            uint32_t ab = sbase + s1 * 32768u;
            uint32_t bb = ab + 16384u;
            const char* ag = Ag + (size_t)(it + 2) * 128;
            const char* bg = Bg + (size_t)(it + 2) * 128;
#pragma unroll
            for (int i = 0; i < 4; ++i) {
                cp16(ab + sw128(soff + i * 16), ag + i * 16);
                cp16(bb + sw128(soff + i * 16), bg + i * 16);
            }
            cp_commit();
        }

        const int s = it % 3;
        const uint32_t ab = sbase + s * 32768u;
        const uint32_t bb = ab + 16384u;

#pragma unroll
        for (int kk = 0; kk < 4; ++kk) {
            uint32_t Ar[4][4];
            uint32_t Br[2][4];
#pragma unroll
            for (int i = 0; i < 4; ++i)
                LDSM4(Ar[i], ab + sw128((uint32_t)(a_r + i * 16) * 128u + kk * 32 + a_cb));
#pragma unroll
            for (int j2 = 0; j2 < 2; ++j2)
                LDSM4(Br[j2], bb + sw128((uint32_t)(b_r + j2 * 16) * 128u + kk * 32 + b_cb));
#pragma unroll
            for (int i = 0; i < 4; ++i)
#pragma unroll
                for (int j = 0; j < 4; ++j)
                    mma_bf16(acc[i][j], Ar[i], Br[j >> 1][(j & 1) * 2], Br[j >> 1][(j & 1) * 2 + 1]);
        }
    }

    const int fr = lid >> 2;
    const int fc = (lid & 3) * 2;
#pragma unroll
    for (int j = 0; j < 4; ++j) {
        const int col = N0 + wn + j * 8 + fc;
        const float bx = bias[col];
        const float by = bias[col + 1];
#pragma unroll
        for (int i = 0; i < 4; ++i) {
            const int row = M0 + wm + i * 16 + fr;
            float2 v0 = make_float2(acc[i][j][0] + bx, acc[i][j][1] + by);
            float2 v1 = make_float2(acc[i][j][2] + bx, acc[i][j][3] + by);
            *reinterpret_cast<float2*>(C + (size_t)row * N + col) = v0;
            *reinterpret_cast<float2*>(C + (size_t)(row + 8) * N + col) = v1;
        }
    }
}

// ---------------------------------------------------------------------------
// Conversions (round-5 versions)
// ---------------------------------------------------------------------------
__global__ __launch_bounds__(256)
void convA_kernel(const float* __restrict__ src, __nv_bfloat16* __restrict__ dst) {
    int i = blockIdx.x * 256 + threadIdx.x;
    int m = i >> 9;
    int j = (i & 511) * 4;
    float4 a = *reinterpret_cast<const float4*>(src + (size_t)m * EMB + j);
    float v[4] = {a.x, a.y, a.z, a.w};
    __nv_bfloat16 h[4], l[4];
#pragma unroll
    for (int q = 0; q < 4; ++q) {
        h[q] = __float2bfloat16(v[q]);
        l[q] = __float2bfloat16(v[q] - __bfloat162float(h[q]));
    }
    __nv_bfloat16* d0 = dst + (size_t)m * K3 + j;
    __nv_bfloat162 h01 = __halves2bfloat162(h[0], h[1]);
    __nv_bfloat162 h23 = __halves2bfloat162(h[2], h[3]);
    __nv_bfloat162 l01 = __halves2bfloat162(l[0], l[1]);
    __nv_bfloat162 l23 = __halves2bfloat162(l[2], l[3]);
    *reinterpret_cast<__nv_bfloat162*>(d0 + 0) = h01;
    *reinterpret_cast<__nv_bfloat162*>(d0 + 2) = h23;
    *reinterpret_cast<__nv_bfloat162*>(d0 + 2048 + 0) = l01;
    *reinterpret_cast<__nv_bfloat162*>(d0 + 2048 + 2) = l23;
    *reinterpret_cast<__nv_bfloat162*>(d0 + 4096 + 0) = h01;
    *reinterpret_cast<__nv_bfloat162*>(d0 + 4096 + 2) = h23;
}

__global__ __launch_bounds__(1024)
void convB_kernel(const float* __restrict__ src, __nv_bfloat16* __restrict__ dst, int Ncols) {
    __shared__ float tile[32][33];
    const int k0 = blockIdx.y * 32;
    const int n0 = blockIdx.x * 32;
    const int tx = threadIdx.x;
    const int ty = threadIdx.y;
    tile[ty][tx] = src[(size_t)(k0 + ty) * Ncols + n0 + tx];
    __syncthreads();
    float v = tile[tx][ty];
    __nv_bfloat16 h = __float2bfloat16(v);
    __nv_bfloat16 lo = __float2bfloat16(v - __bfloat162float(h));
    size_t drow = (size_t)(n0 + ty) * K3 + k0 + tx;
    dst[drow + 0]    = h;
    dst[drow + 2048] = h;
    dst[drow + 4096] = lo;
}

// ---------------------------------------------------------------------------
// RoPE + split -> bf16 Q (pre-scaled by 0.125), K, Vh, Vl
// ---------------------------------------------------------------------------
__global__ __launch_bounds__(256)
void rope_split_kernel() {
    int idx = blockIdx.x * blockDim.x + threadIdx.x;
    int d = idx & 63;
    int h = (idx >> 6) & 31;
    int b = (idx >> 11) & 1;
    int s = idx >> 12;

    const float* base = g_qkv + (size_t)(s * BATCH + b) * QKV_N;
    int col = h * HDIM + d;

    float qv = base[col];
    float kv = base[EMB + col];
    float vv = base[2 * EMB + col];

    int i = d & 31;
    float inv_freq = __expf(-0.28782252f * (float)i);
    float ang = (float)s * inv_freq;
    float sn, cs;
    sincosf(ang, &sn, &cs);

    float qpair, kpair;
    if (d < 32) {
        qpair = -base[col + 32];
        kpair = -base[EMB + col + 32];
    } else {
        qpair = base[col - 32];
        kpair = base[EMB + col - 32];
    }

    float qr = qv * cs + qpair * sn;
    float kr = kv * cs + kpair * sn;

    size_t o = ((size_t)(b * HEADS + h) * S_LEN + s) * HDIM + d;
    g_qb[o] = __float2bfloat16(qr * 0.125f);   // fold softmax scale (exact pow2)
    g_kb[o] = __float2bfloat16(kr);
    __nv_bfloat16 vh = __float2bfloat16(vv);
    g_vhb[o] = vh;
    g_vlb[o] = __float2bfloat16(vv - __bfloat162float(vh));
}

// ---------------------------------------------------------------------------
// HMMA flash attention. Grid (16, B*H), 256 threads = 8 warps.
// Warp w owns query rows [w*16, w*16+16). 64-key tiles, double-buffered
// cp.async (K, Vh, Vl). QK in bf16; PV = Ph*Vh + Ph*Vl + Pl*Vh with P
// kept in registers via the C-frag == A-frag identity. V^T fragments via
// ldmatrix.trans. smem 64KB: Q 16KB + 2 x (K 8 + Vh 8 + Vl 8).
// ---------------------------------------------------------------------------
#define ATTN_SMEM 65536

__global__ __launch_bounds__(256, 2)
void attn_kernel() {
    extern __shared__ char smc[];
    const uint32_t sQ = smem_u32(smc);

    const int bh = blockIdx.y;
    const int qt = 15 - (int)blockIdx.x;      // longest-first
    const int q0 = qt * 128;
    const int t  = threadIdx.x;
    const int w  = t >> 5;
    const int lid = t & 31;

    const __nv_bfloat16* Qg  = g_qb  + (size_t)bh * S_LEN * HDIM;
    const __nv_bfloat16* Kg  = g_kb  + (size_t)bh * S_LEN * HDIM;
    const __nv_bfloat16* Vhg = g_vhb + (size_t)bh * S_LEN * HDIM;
    const __nv_bfloat16* Vlg = g_vlb + (size_t)bh * S_LEN * HDIM;

    // prologue: Q tile (128 rows x 128B) + key-tile 0 into buffer 0
    {
        const int row = t >> 1;
        const int half = (t & 1) * 64;
        const char* src = (const char*)(Qg + (size_t)(q0 + row) * HDIM) + half;
#pragma unroll
        for (int i = 0; i < 4; ++i)
            cp16(sQ + sw128((uint32_t)row * 128u + half + i * 16), src + i * 16);
    }
    {
        const int row = t >> 2;
        const int qo = (t & 3) * 32;
        const uint32_t so = sw128((uint32_t)row * 128u + qo);
        const uint32_t so2 = sw128((uint32_t)row * 128u + qo + 16);
        const char* kg = (const char*)(Kg + (size_t)row * HDIM) + qo;
        const char* vh = (const char*)(Vhg + (size_t)row * HDIM) + qo;
        const char* vl = (const char*)(Vlg + (size_t)row * HDIM) + qo;
        uint32_t bK = sQ + 16384u;
        cp16(bK + so, kg);           cp16(bK + so2, kg + 16);
        cp16(bK + 8192u + so, vh);   cp16(bK + 8192u + so2, vh + 16);
        cp16(bK + 16384u + so, vl);  cp16(bK + 16384u + so2, vl + 16);
    }
    cp_commit();

    float oc[8][4];
#pragma unroll
    for (int jn = 0; jn < 8; ++jn)
#pragma unroll
        for (int q = 0; q < 4; ++q) oc[jn][q] = 0.0f;
    float m[2] = {-1e30f, -1e30f};
    float l[2] = {0.0f, 0.0f};

    const int nkt = 2 * qt + 2;
#pragma unroll 1
    for (int kt = 0; kt < nkt; ++kt) {
        if (kt + 1 < nkt) {
            const int k1 = (kt + 1) * 64;
            const int row = t >> 2;
            const int qo = (t & 3) * 32;
            const uint32_t so = sw128((uint32_t)row * 128u + qo);
            const uint32_t so2 = sw128((uint32_t)row * 128u + qo + 16);
            const char* kg = (const char*)(Kg + (size_t)(k1 + row) * HDIM) + qo;
            const char* vh = (const char*)(Vhg + (size_t)(k1 + row) * HDIM) + qo;
            const char* vl = (const char*)(Vlg + (size_t)(k1 + row) * HDIM) + qo;
            uint32_t bK = sQ + 16384u + ((kt + 1) & 1) * 24576u;
            cp16(bK + so, kg);           cp16(bK + so2, kg + 16);
            cp16(bK + 8192u + so, vh);   cp16(bK + 8192u + so2, vh + 16);
            cp16(bK + 16384u + so, vl);  cp16(bK + 16384u + so2, vl + 16);
            cp_commit();
            asm volatile("cp.async.wait_group 1;" ::: "memory");
        } else {
            asm volatile("cp.async.wait_group 0;" ::: "memory");
        }
        __syncthreads();

        const uint32_t bK  = sQ + 16384u + (kt & 1) * 24576u;
        const uint32_t bVh = bK + 8192u;
        const uint32_t bVl = bK + 16384u;
        const int k0 = kt * 64;

        // ---- QK: sc[jn][0..3] = scores, m16 x n64 per warp ----
        float sc[8][4];
#pragma unroll
        for (int jn = 0; jn < 8; ++jn)
#pragma unroll
            for (int q = 0; q < 4; ++q) sc[jn][q] = 0.0f;

#pragma unroll
        for (int k4 = 0; k4 < 4; ++k4) {
            uint32_t QA[4];
            LDSM4(QA, sQ + sw128((uint32_t)(w * 16 + (lid & 15)) * 128u + k4 * 32 + (lid >> 4) * 16));
#pragma unroll
            for (int j2 = 0; j2 < 4; ++j2) {
                uint32_t KB[4];
                LDSM4(KB, bK + sw128((uint32_t)((lid & 7) + ((lid >> 4) << 3) + j2 * 16) * 128u
                                     + k4 * 32 + ((lid >> 3) & 1) * 16));
                mma_bf16(sc[j2 * 2 + 0], QA, KB[0], KB[1]);
                mma_bf16(sc[j2 * 2 + 1], QA, KB[2], KB[3]);
            }
        }

        // ---- causal mask (only tiles near/over the diagonal) ----
        if (k0 + 63 > q0 + w * 16) {
            const int rlo = q0 + w * 16 + (lid >> 2);
#pragma unroll
            for (int jn = 0; jn < 8; ++jn) {
                const int cb = k0 + jn * 8 + (lid & 3) * 2;
#pragma unroll
                for (int q = 0; q < 4; ++q) {
                    const int colg = cb + (q & 1);
                    const int rowg = rlo + (q >> 1) * 8;
                    if (colg > rowg) sc[jn][q] += MASK_NEG;
                }
            }
        }

        // ---- online softmax per row-half ----
#pragma unroll
        for (int hh = 0; hh < 2; ++hh) {
            float mt = sc[0][hh * 2];
#pragma unroll
            for (int jn = 0; jn < 8; ++jn)
                mt = fmaxf(mt, fmaxf(sc[jn][hh * 2], sc[jn][hh * 2 + 1]));
            mt = fmaxf(mt, __shfl_xor_sync(0xffffffffu, mt, 1));
            mt = fmaxf(mt, __shfl_xor_sync(0xffffffffu, mt, 2));

            const float mn = fmaxf(m[hh], mt);
            const float corr = __expf(m[hh] - mn);
            float ps = 0.0f;
#pragma unroll
            for (int jn = 0; jn < 8; ++jn) {
                float p0 = __expf(sc[jn][hh * 2] - mn);
                float p1 = __expf(sc[jn][hh * 2 + 1] - mn);
                sc[jn][hh * 2] = p0;
                sc[jn][hh * 2 + 1] = p1;
                ps += p0 + p1;
            }
            ps += __shfl_xor_sync(0xffffffffu, ps, 1);
            ps += __shfl_xor_sync(0xffffffffu, ps, 2);
            l[hh] = l[hh] * corr + ps;
            m[hh] = mn;
#pragma unroll
            for (int jn = 0; jn < 8; ++jn) {
                oc[jn][hh * 2] *= corr;
                oc[jn][hh * 2 + 1] *= corr;
            }
        }

        // ---- PV: oc += Ph*Vh + Ph*Vl + Pl*Vh ----
#pragma unroll
        for (int k4 = 0; k4 < 4; ++k4) {
            uint32_t PhA[4], PlA[4];
            {
                float r0, r1, r2, r3, r4, r5, r6, r7;
                PhA[0] = packlo(sc[2 * k4][0], sc[2 * k4][1], r0, r1);
                PhA[1] = packlo(sc[2 * k4][2], sc[2 * k4][3], r2, r3);
                PhA[2] = packlo(sc[2 * k4 + 1][0], sc[2 * k4 + 1][1], r4, r5);
                PhA[3] = packlo(sc[2 * k4 + 1][2], sc[2 * k4 + 1][3], r6, r7);
                PlA[0] = packb(r0, r1);
                PlA[1] = packb(r2, r3);
                PlA[2] = packb(r4, r5);
                PlA[3] = packb(r6, r7);
            }
            const uint32_t voff = sw128((uint32_t)(k4 * 16 + (lid & 15)) * 128u + (lid >> 4) * 16);
#pragma unroll
            for (int j2 = 0; j2 < 4; ++j2) {
                uint32_t VhB[4], VlB[4];
                LDSM4T(VhB, bVh + sw128((uint32_t)(k4 * 16 + (lid & 15)) * 128u + j2 * 32 + (lid >> 4) * 16));
                LDSM4T(VlB, bVl + sw128((uint32_t)(k4 * 16 + (lid & 15)) * 128u + j2 * 32 + (lid >> 4) * 16));
                mma_bf16(oc[j2 * 2 + 0], PhA, VhB[0], VhB[1]);
                mma_bf16(oc[j2 * 2 + 1], PhA, VhB[2], VhB[3]);
                mma_bf16(oc[j2 * 2 + 0], PhA, VlB[0], VlB[1]);
                mma_bf16(oc[j2 * 2 + 1], PhA, VlB[2], VlB[3]);
                mma_bf16(oc[j2 * 2 + 0], PlA, VhB[0], VhB[1]);
                mma_bf16(oc[j2 * 2 + 1], PlA, VhB[2], VhB[3]);
            }
            (void)voff;
        }
        __syncthreads();   // all warps done with this buffer before it is refilled
    }

    // ---- epilogue: normalize, write ctx fp32 ----
    const int b = bh >> 5;
    const int h = bh & 31;
#pragma unroll
    for (int hh = 0; hh < 2; ++hh) {
        const int row = q0 + w * 16 + (lid >> 2) + hh * 8;
        const float invl = 1.0f / l[hh];
        float* dst = g_ctx + (size_t)(row * BATCH + b) * EMB + h * HDIM;
#pragma unroll
        for (int jn = 0; jn < 8; ++jn) {
            float2 v = make_float2(oc[jn][hh * 2] * invl, oc[jn][hh * 2 + 1] * invl);
            *reinterpret_cast<float2*>(dst + jn * 8 + (lid & 3) * 2) = v;
        }
    }
}

// ---------------------------------------------------------------------------
// Launch
// ---------------------------------------------------------------------------
extern "C" void kernel_launch(void* const* d_in, const int* in_sizes, int n_in,
                              void* d_out, int out_size) {
    const float* hs    = (const float*)d_in[0];
    const float* qkv_w = (const float*)d_in[1];
    const float* qkv_b = (const float*)d_in[2];
    const float* out_w = (const float*)d_in[3];
    const float* out_b = (const float*)d_in[4];
    float* out = (float*)d_out;

    cudaFuncSetAttribute(gemm_mma_bf16, cudaFuncAttributeMaxDynamicSharedMemorySize, GEMM_SMEM);
    cudaFuncSetAttribute(attn_kernel, cudaFuncAttributeMaxDynamicSharedMemorySize, ATTN_SMEM);

    float *qkv, *ctx;
    __nv_bfloat16 *A3, *B3q, *B3o;
    cudaGetSymbolAddress((void**)&qkv, g_qkv);
    cudaGetSymbolAddress((void**)&ctx, g_ctx);
    cudaGetSymbolAddress((void**)&A3,  g_A3);
    cudaGetSymbolAddress((void**)&B3q, g_B3q);
    cudaGetSymbolAddress((void**)&B3o, g_B3o);

    // Weight conversions (transpose + hi/lo split)
    {
        dim3 blk(32, 32);
        convB_kernel<<<dim3(QKV_N / 32, EMB / 32), blk>>>(qkv_w, B3q, QKV_N);
        convB_kernel<<<dim3(EMB / 32, EMB / 32), blk>>>(out_w, B3o, EMB);
    }
    convA_kernel<<<MROWS * 512 / 256, 256>>>(hs, A3);

    // 1. QKV projection (HMMA split-bf16, round-5 config)
    gemm_mma_bf16<<<dim3(QKV_N / 128, MROWS / 128), 256, GEMM_SMEM>>>(QKV_N, A3, B3q, qkv_b, qkv);

    // 2. RoPE + split -> bf16 Q/K/Vh/Vl
    rope_split_kernel<<<(S_LEN * BATCH * HEADS * HDIM) / 256, 256>>>();

    // 3. Causal attention (HMMA flash)
    attn_kernel<<<dim3(S_LEN / 128, BATCH * HEADS), 256, ATTN_SMEM>>>();

    // 4. ctx conversion + output projection
    convA_kernel<<<MROWS * 512 / 256, 256>>>(ctx, A3);
    gemm_mma_bf16<<<dim3(EMB / 128, MROWS / 128), 256, GEMM_SMEM>>>(EMB, A3, B3o, out_b, out);
}